// round 13
// baseline (speedup 1.0000x reference)
#include <cuda_runtime.h>
#include <cuda_fp16.h>
#include <math.h>

#define NUM_STEPS 30
#define MAX_VOL (2 * 192 * 192 * 192)   // 14,155,776 voxels -> 113MB static

typedef unsigned long long ull;

// interleaved fp16 volume: half4 {c0, c1, c2, 0} per voxel, per batch
__device__ ull g_vol[MAX_VOL];

// ---------------------------------------------------------------------------
// packed f32x2 helpers (sm_103a)
// ---------------------------------------------------------------------------
__device__ __forceinline__ ull pack2(float lo, float hi) {
    ull r; asm("mov.b64 %0, {%1, %2};" : "=l"(r) : "f"(lo), "f"(hi)); return r;
}
__device__ __forceinline__ void unpack2(ull v, float& lo, float& hi) {
    asm("mov.b64 {%0, %1}, %2;" : "=f"(lo), "=f"(hi) : "l"(v));
}
__device__ __forceinline__ ull mul2(ull a, ull b) {
    ull r; asm("mul.rn.f32x2 %0, %1, %2;" : "=l"(r) : "l"(a), "l"(b)); return r;
}
__device__ __forceinline__ ull fma2(ull a, ull b, ull c) {
    ull r; asm("fma.rn.f32x2 %0, %1, %2, %3;" : "=l"(r) : "l"(a), "l"(b), "l"(c)); return r;
}
__device__ __forceinline__ ull lerp2(ull a, ull b, ull t, ull omt) {
    return fma2(b, t, mul2(a, omt));
}

// ---------------------------------------------------------------------------
// fp32 Gauss-Jordan 4x4 inverse (well-conditioned input)
// ---------------------------------------------------------------------------
__device__ void inv4x4_f32(const float* __restrict__ A, float* __restrict__ out) {
    float m[4][8];
    #pragma unroll
    for (int i = 0; i < 4; i++) {
        #pragma unroll
        for (int j = 0; j < 4; j++) m[i][j] = A[i * 4 + j];
        #pragma unroll
        for (int j = 0; j < 4; j++) m[i][4 + j] = (i == j) ? 1.0f : 0.0f;
    }
    #pragma unroll
    for (int col = 0; col < 4; col++) {
        int piv = col;
        float best = fabsf(m[col][col]);
        #pragma unroll
        for (int r = 0; r < 4; r++) {
            if (r > col) {
                float v = fabsf(m[r][col]);
                if (v > best) { best = v; piv = r; }
            }
        }
        if (piv != col) {
            #pragma unroll
            for (int j = 0; j < 8; j++) { float t = m[col][j]; m[col][j] = m[piv][j]; m[piv][j] = t; }
        }
        float inv = 1.0f / m[col][col];
        #pragma unroll
        for (int j = 0; j < 8; j++) m[col][j] *= inv;
        #pragma unroll
        for (int r = 0; r < 4; r++) {
            if (r != col) {
                float f = m[r][col];
                #pragma unroll
                for (int j = 0; j < 8; j++) m[r][j] = fmaf(-f, m[col][j], m[r][j]);
            }
        }
    }
    #pragma unroll
    for (int i = 0; i < 4; i++)
        #pragma unroll
        for (int j = 0; j < 4; j++)
            out[i * 4 + j] = m[i][4 + j];
}

// ---------------------------------------------------------------------------
// conversion: [B,3,D,H,W] f32 -> interleaved half4 (streaming, coalesced)
// ---------------------------------------------------------------------------
__global__ __launch_bounds__(256)
void conv_kernel(const float* __restrict__ flow, int DHW) {
    int r = blockIdx.x * 256 + threadIdx.x;
    if (r >= DHW) return;
    int b = blockIdx.y;
    const float* p = flow + (size_t)b * 3 * (size_t)DHW;
    float c0 = __ldg(p + r);
    float c1 = __ldg(p + r + DHW);
    float c2 = __ldg(p + r + 2 * DHW);
    __half2 lo = __floats2half2_rn(c0, c1);
    __half2 hi = __floats2half2_rn(c2, 0.0f);
    unsigned ulo = *reinterpret_cast<unsigned*>(&lo);
    unsigned uhi = *reinterpret_cast<unsigned*>(&hi);
    g_vol[(size_t)b * DHW + r] = (ull)ulo | ((ull)uhi << 32);
}

// ---------------------------------------------------------------------------
// main integration kernel — interleaved fp16 corner loads (1 load/corner)
// ---------------------------------------------------------------------------
__global__ __launch_bounds__(128, 8)
void deform_h4_kernel(const float* __restrict__ verts,
                      const float* __restrict__ affine,
                      float* __restrict__ out,
                      int B, int N, int D, int H, int W)
{
    __shared__ float s_inv[2][16];

    int gid = blockIdx.x * blockDim.x + threadIdx.x;
    long long total = (long long)B * N;

    long long g0 = (long long)blockIdx.x * blockDim.x;
    long long g1 = min(g0 + blockDim.x - 1, total - 1);
    int bmin = (int)(g0 / N);
    int bmax = (int)(g1 / N);

    if (threadIdx.x == 0) {
        inv4x4_f32(affine + bmin * 16, s_inv[0]);
        if (bmax != bmin) inv4x4_f32(affine + bmax * 16, s_inv[1]);
    }
    __syncthreads();

    if (gid >= total) return;
    int b = gid / N;
    int n = gid - b * N;

    // ---- affine transform ----
    const float* A = affine + b * 16;
    size_t vbase = ((size_t)b * N + n) * 3;
    float vx = verts[vbase + 0];
    float vy = verts[vbase + 1];
    float vz = verts[vbase + 2];

    float px = A[0] * vx + A[1] * vy + A[2]  * vz + A[3];
    float py = A[4] * vx + A[5] * vy + A[6]  * vz + A[7];
    float pz = A[8] * vx + A[9] * vy + A[10] * vz + A[11];

    const int HW  = H * W;
    const int DHW = D * HW;
    const ull* vol = g_vol + (size_t)b * (size_t)DHW;
    const float scale = 1.0f / (float)NUM_STEPS;
    const float dmax = (float)(D - 1), hmax = (float)(H - 1), wmax = (float)(W - 1);

    float xd = px, xh = py, xw = pz;

    float cfd = 1e30f, cfh = 1e30f, cfw = 1e30f;
    int cell = -1;
    ull  c01[8];
    float c2[8];

    #pragma unroll 1
    for (int s = 0; s < NUM_STEPS; s++) {
        float fd = xd - cfd;
        float fh = xh - cfh;
        float fw = xw - cfw;

        float mn = fminf(fd, fminf(fh, fw));
        float mx = fmaxf(fd, fmaxf(fh, fw));
        if (!(mn >= 0.0f && mx < 1.0f)) {
            float pdc = fminf(fmaxf(xd, 0.0f), dmax);
            float phc = fminf(fmaxf(xh, 0.0f), hmax);
            float pwc = fminf(fmaxf(xw, 0.0f), wmax);
            float fd0 = floorf(pdc), fh0 = floorf(phc), fw0 = floorf(pwc);
            int d0 = (int)fd0, h0 = (int)fh0, w0 = (int)fw0;
            fd = pdc - fd0; fh = phc - fh0; fw = pwc - fw0;
            cfd = fd0; cfh = fh0; cfw = fw0;

            int ncell = (d0 << 20) | (h0 << 10) | w0;
            if (ncell != cell) {
                cell = ncell;
                int d1 = min(d0 + 1, D - 1);
                int h1 = min(h0 + 1, H - 1);
                int w1 = min(w0 + 1, W - 1);
                int rd0 = d0 * HW, rd1 = d1 * HW;
                int rh0 = h0 * W,  rh1 = h1 * W;
                int o[8];
                o[0] = rd0 + rh0 + w0; o[1] = rd0 + rh0 + w1;
                o[2] = rd0 + rh1 + w0; o[3] = rd0 + rh1 + w1;
                o[4] = rd1 + rh0 + w0; o[5] = rd1 + rh0 + w1;
                o[6] = rd1 + rh1 + w0; o[7] = rd1 + rh1 + w1;
                #pragma unroll
                for (int k = 0; k < 8; k++) {
                    ull v = __ldg(vol + o[k]);
                    unsigned ulo = (unsigned)v;
                    unsigned uhi = (unsigned)(v >> 32);
                    __half2 hlo = *reinterpret_cast<__half2*>(&ulo);
                    __half2 hhi = *reinterpret_cast<__half2*>(&uhi);
                    float2 f01 = __half22float2(hlo);
                    c01[k] = pack2(f01.x, f01.y);
                    c2[k]  = __low2float(hhi);
                }
            }
        }

        float omfw = 1.0f - fw, omfh = 1.0f - fh, omfd = 1.0f - fd;
        ull W2  = pack2(fw, fw),   OW2 = pack2(omfw, omfw);
        ull H2  = pack2(fh, fh),   OH2 = pack2(omfh, omfh);
        ull D2  = pack2(fd, fd),   OD2 = pack2(omfd, omfd);

        ull l00 = lerp2(c01[0], c01[1], W2, OW2);
        ull l01 = lerp2(c01[2], c01[3], W2, OW2);
        ull l10 = lerp2(c01[4], c01[5], W2, OW2);
        ull l11 = lerp2(c01[6], c01[7], W2, OW2);
        ull m0  = lerp2(l00, l01, H2, OH2);
        ull m1  = lerp2(l10, l11, H2, OH2);
        ull r01 = lerp2(m0, m1, D2, OD2);
        float s0, s1;
        unpack2(r01, s0, s1);

        float q00 = c2[0] * omfw + c2[1] * fw;
        float q01 = c2[2] * omfw + c2[3] * fw;
        float q10 = c2[4] * omfw + c2[5] * fw;
        float q11 = c2[6] * omfw + c2[7] * fw;
        float q0  = q00 * omfh + q01 * fh;
        float q1  = q10 * omfh + q11 * fh;
        float s2  = q0 * omfd + q1 * fd;

        xd = fmaf(s0, scale, xd);
        xh = fmaf(s1, scale, xh);
        xw = fmaf(s2, scale, xw);
    }

    // ---- outputs ----
    float fix = xd - px, fiy = xh - py, fiz = xw - pz;

    const float* Inv = s_inv[b - bmin];
    float ox = Inv[0] * xd + Inv[1] * xh + Inv[2]  * xw + Inv[3];
    float oy = Inv[4] * xd + Inv[5] * xh + Inv[6]  * xw + Inv[7];
    float oz = Inv[8] * xd + Inv[9] * xh + Inv[10] * xw + Inv[11];

    size_t pb = ((size_t)b * N + n) * 3;
    out[pb + 0] = ox;
    out[pb + 1] = oy;
    out[pb + 2] = oz;

    size_t fb = (size_t)B * N * 3 + ((size_t)b * 3) * (size_t)N + n;
    out[fb + 0 * (size_t)N] = fix;
    out[fb + 1 * (size_t)N] = fiy;
    out[fb + 2 * (size_t)N] = fiz;
}

// ---------------------------------------------------------------------------
// fallback: round-9 fp32 kernel (shapes that don't fit g_vol)
// ---------------------------------------------------------------------------
__global__ __launch_bounds__(128, 8)
void deform_plain_kernel(const float* __restrict__ verts,
                         const float* __restrict__ affine,
                         const float* __restrict__ flow,
                         float* __restrict__ out,
                         int B, int N, int D, int H, int W)
{
    __shared__ float s_inv[2][16];
    int gid = blockIdx.x * blockDim.x + threadIdx.x;
    long long total = (long long)B * N;
    long long g0 = (long long)blockIdx.x * blockDim.x;
    long long g1 = min(g0 + blockDim.x - 1, total - 1);
    int bmin = (int)(g0 / N);
    int bmax = (int)(g1 / N);
    if (threadIdx.x == 0) {
        inv4x4_f32(affine + bmin * 16, s_inv[0]);
        if (bmax != bmin) inv4x4_f32(affine + bmax * 16, s_inv[1]);
    }
    __syncthreads();
    if (gid >= total) return;
    int b = gid / N, n = gid - b * N;

    const float* A = affine + b * 16;
    size_t vbase = ((size_t)b * N + n) * 3;
    float vx = verts[vbase + 0], vy = verts[vbase + 1], vz = verts[vbase + 2];
    float px = A[0]*vx + A[1]*vy + A[2] *vz + A[3];
    float py = A[4]*vx + A[5]*vy + A[6] *vz + A[7];
    float pz = A[8]*vx + A[9]*vy + A[10]*vz + A[11];

    const int HW = H * W, DHW = D * HW;
    const float* base = flow + (size_t)b * 3 * (size_t)DHW;
    const float scale = 1.0f / (float)NUM_STEPS;
    const float dmax = (float)(D - 1), hmax = (float)(H - 1), wmax = (float)(W - 1);

    float xd = px, xh = py, xw = pz;
    float cfd = 1e30f, cfh = 1e30f, cfw = 1e30f;
    int cell = -1;
    ull c01[8]; float c2[8];

    #pragma unroll 1
    for (int s = 0; s < NUM_STEPS; s++) {
        float fd = xd - cfd, fh = xh - cfh, fw = xw - cfw;
        float mn = fminf(fd, fminf(fh, fw));
        float mx = fmaxf(fd, fmaxf(fh, fw));
        if (!(mn >= 0.0f && mx < 1.0f)) {
            float pdc = fminf(fmaxf(xd, 0.0f), dmax);
            float phc = fminf(fmaxf(xh, 0.0f), hmax);
            float pwc = fminf(fmaxf(xw, 0.0f), wmax);
            float fd0 = floorf(pdc), fh0 = floorf(phc), fw0 = floorf(pwc);
            int d0 = (int)fd0, h0 = (int)fh0, w0 = (int)fw0;
            fd = pdc - fd0; fh = phc - fh0; fw = pwc - fw0;
            cfd = fd0; cfh = fh0; cfw = fw0;
            int ncell = (d0 << 20) | (h0 << 10) | w0;
            if (ncell != cell) {
                cell = ncell;
                int d1 = min(d0 + 1, D - 1);
                int h1 = min(h0 + 1, H - 1);
                int w1 = min(w0 + 1, W - 1);
                int rd0 = d0 * HW, rd1 = d1 * HW;
                int rh0 = h0 * W,  rh1 = h1 * W;
                int o[8];
                o[0] = rd0 + rh0 + w0; o[1] = rd0 + rh0 + w1;
                o[2] = rd0 + rh1 + w0; o[3] = rd0 + rh1 + w1;
                o[4] = rd1 + rh0 + w0; o[5] = rd1 + rh0 + w1;
                o[6] = rd1 + rh1 + w0; o[7] = rd1 + rh1 + w1;
                const float* p0 = base;
                const float* p1 = base + DHW;
                const float* p2 = base + 2 * DHW;
                #pragma unroll
                for (int k = 0; k < 8; k++) {
                    float a0 = __ldg(p0 + o[k]);
                    float a1 = __ldg(p1 + o[k]);
                    c2[k]  = __ldg(p2 + o[k]);
                    c01[k] = pack2(a0, a1);
                }
            }
        }
        float omfw = 1.0f - fw, omfh = 1.0f - fh, omfd = 1.0f - fd;
        ull W2 = pack2(fw, fw), OW2 = pack2(omfw, omfw);
        ull H2 = pack2(fh, fh), OH2 = pack2(omfh, omfh);
        ull D2 = pack2(fd, fd), OD2 = pack2(omfd, omfd);
        ull l00 = lerp2(c01[0], c01[1], W2, OW2);
        ull l01 = lerp2(c01[2], c01[3], W2, OW2);
        ull l10 = lerp2(c01[4], c01[5], W2, OW2);
        ull l11 = lerp2(c01[6], c01[7], W2, OW2);
        ull m0 = lerp2(l00, l01, H2, OH2);
        ull m1 = lerp2(l10, l11, H2, OH2);
        ull r01 = lerp2(m0, m1, D2, OD2);
        float s0, s1; unpack2(r01, s0, s1);
        float q00 = c2[0]*omfw + c2[1]*fw;
        float q01 = c2[2]*omfw + c2[3]*fw;
        float q10 = c2[4]*omfw + c2[5]*fw;
        float q11 = c2[6]*omfw + c2[7]*fw;
        float q0 = q00*omfh + q01*fh;
        float q1 = q10*omfh + q11*fh;
        float s2 = q0*omfd + q1*fd;
        xd = fmaf(s0, scale, xd);
        xh = fmaf(s1, scale, xh);
        xw = fmaf(s2, scale, xw);
    }

    float fix = xd - px, fiy = xh - py, fiz = xw - pz;
    const float* Inv = s_inv[b - bmin];
    float ox = Inv[0]*xd + Inv[1]*xh + Inv[2] *xw + Inv[3];
    float oy = Inv[4]*xd + Inv[5]*xh + Inv[6] *xw + Inv[7];
    float oz = Inv[8]*xd + Inv[9]*xh + Inv[10]*xw + Inv[11];
    size_t pb = ((size_t)b * N + n) * 3;
    out[pb + 0] = ox; out[pb + 1] = oy; out[pb + 2] = oz;
    size_t fb = (size_t)B * N * 3 + ((size_t)b * 3) * (size_t)N + n;
    out[fb + 0 * (size_t)N] = fix;
    out[fb + 1 * (size_t)N] = fiy;
    out[fb + 2 * (size_t)N] = fiz;
}

extern "C" void kernel_launch(void* const* d_in, const int* in_sizes, int n_in,
                              void* d_out, int out_size) {
    const float* verts  = (const float*)d_in[0];
    const float* affine = (const float*)d_in[1];
    const float* flow   = (const float*)d_in[2];
    float* out = (float*)d_out;

    int B = in_sizes[1] / 16;
    int N = in_sizes[0] / (3 * B);
    long long dhw = (long long)in_sizes[2] / (3LL * B);
    int D = (int)llrint(cbrt((double)dhw));
    int H = D, W = D;

    long long total = (long long)B * N;
    int threads = 128;
    int blocks = (int)((total + threads - 1) / threads);

    int DHW = D * H * W;
    if ((long long)B * DHW <= (long long)MAX_VOL && B <= 2 &&
        D <= 1023 && H <= 1023 && W <= 1023) {
        dim3 cgrid((DHW + 255) / 256, B, 1);
        conv_kernel<<<cgrid, 256>>>(flow, DHW);
        deform_h4_kernel<<<blocks, threads>>>(verts, affine, out, B, N, D, H, W);
    } else {
        deform_plain_kernel<<<blocks, threads>>>(verts, affine, flow, out,
                                                 B, N, D, H, W);
    }
}

// round 14
// speedup vs baseline: 1.1480x; 1.1480x over previous
#include <cuda_runtime.h>
#include <cuda_fp16.h>
#include <math.h>

#define NUM_STEPS 30
#define MAX_VOL (2 * 192 * 192 * 192)   // 14,155,776 voxels -> 113MB static

typedef unsigned long long ull;

// interleaved fp16 volume: half4 {c0, c1, c2, 0} per voxel, per batch
__device__ ull g_vol[MAX_VOL];

// ---------------------------------------------------------------------------
// packed f32x2 helpers (sm_103a)
// ---------------------------------------------------------------------------
__device__ __forceinline__ ull pack2(float lo, float hi) {
    ull r; asm("mov.b64 %0, {%1, %2};" : "=l"(r) : "f"(lo), "f"(hi)); return r;
}
__device__ __forceinline__ void unpack2(ull v, float& lo, float& hi) {
    asm("mov.b64 {%0, %1}, %2;" : "=f"(lo), "=f"(hi) : "l"(v));
}
__device__ __forceinline__ ull fma2(ull a, ull b, ull c) {
    ull r; asm("fma.rn.f32x2 %0, %1, %2, %3;" : "=l"(r) : "l"(a), "l"(b), "l"(c)); return r;
}
// b - a  ==  fma2(a, -1, b)
__device__ __forceinline__ ull sub2(ull b, ull a, ull MONE) {
    return fma2(a, MONE, b);
}

// ---------------------------------------------------------------------------
// fp32 Gauss-Jordan 4x4 inverse (well-conditioned input)
// ---------------------------------------------------------------------------
__device__ void inv4x4_f32(const float* __restrict__ A, float* __restrict__ out) {
    float m[4][8];
    #pragma unroll
    for (int i = 0; i < 4; i++) {
        #pragma unroll
        for (int j = 0; j < 4; j++) m[i][j] = A[i * 4 + j];
        #pragma unroll
        for (int j = 0; j < 4; j++) m[i][4 + j] = (i == j) ? 1.0f : 0.0f;
    }
    #pragma unroll
    for (int col = 0; col < 4; col++) {
        int piv = col;
        float best = fabsf(m[col][col]);
        #pragma unroll
        for (int r = 0; r < 4; r++) {
            if (r > col) {
                float v = fabsf(m[r][col]);
                if (v > best) { best = v; piv = r; }
            }
        }
        if (piv != col) {
            #pragma unroll
            for (int j = 0; j < 8; j++) { float t = m[col][j]; m[col][j] = m[piv][j]; m[piv][j] = t; }
        }
        float inv = 1.0f / m[col][col];
        #pragma unroll
        for (int j = 0; j < 8; j++) m[col][j] *= inv;
        #pragma unroll
        for (int r = 0; r < 4; r++) {
            if (r != col) {
                float f = m[r][col];
                #pragma unroll
                for (int j = 0; j < 8; j++) m[r][j] = fmaf(-f, m[col][j], m[r][j]);
            }
        }
    }
    #pragma unroll
    for (int i = 0; i < 4; i++)
        #pragma unroll
        for (int j = 0; j < 4; j++)
            out[i * 4 + j] = m[i][4 + j];
}

__device__ __forceinline__ ull pack_voxel(float c0, float c1, float c2) {
    __half2 lo = __floats2half2_rn(c0, c1);
    __half2 hi = __floats2half2_rn(c2, 0.0f);
    unsigned ulo = *reinterpret_cast<unsigned*>(&lo);
    unsigned uhi = *reinterpret_cast<unsigned*>(&hi);
    return (ull)ulo | ((ull)uhi << 32);
}

// ---------------------------------------------------------------------------
// conversion: [B,3,D,H,W] f32 -> interleaved half4, 4 voxels per thread
// ---------------------------------------------------------------------------
__global__ __launch_bounds__(256)
void conv_kernel(const float* __restrict__ flow, int DHW) {
    int r = (blockIdx.x * 256 + threadIdx.x) * 4;
    if (r >= DHW) return;
    int b = blockIdx.y;
    const float* p = flow + (size_t)b * 3 * (size_t)DHW;
    ull* dst = g_vol + (size_t)b * (size_t)DHW;

    if (r + 3 < DHW) {
        float4 c0 = __ldg((const float4*)(p + r));
        float4 c1 = __ldg((const float4*)(p + r + DHW));
        float4 c2 = __ldg((const float4*)(p + r + 2 * DHW));
        ulonglong2 o0, o1;
        o0.x = pack_voxel(c0.x, c1.x, c2.x);
        o0.y = pack_voxel(c0.y, c1.y, c2.y);
        o1.x = pack_voxel(c0.z, c1.z, c2.z);
        o1.y = pack_voxel(c0.w, c1.w, c2.w);
        *reinterpret_cast<ulonglong2*>(dst + r)     = o0;
        *reinterpret_cast<ulonglong2*>(dst + r + 2) = o1;
    } else {
        for (int i = r; i < DHW; i++) {
            float c0 = __ldg(p + i);
            float c1 = __ldg(p + i + DHW);
            float c2 = __ldg(p + i + 2 * DHW);
            dst[i] = pack_voxel(c0, c1, c2);
        }
    }
}

// ---------------------------------------------------------------------------
// main integration kernel — fp16 corners, diff-form lerp, 9 CTAs/SM
// ---------------------------------------------------------------------------
__global__ __launch_bounds__(128, 9)
void deform_h4_kernel(const float* __restrict__ verts,
                      const float* __restrict__ affine,
                      float* __restrict__ out,
                      int B, int N, int D, int H, int W)
{
    __shared__ float s_inv[2][16];

    int gid = blockIdx.x * blockDim.x + threadIdx.x;
    long long total = (long long)B * N;

    long long g0 = (long long)blockIdx.x * blockDim.x;
    long long g1 = min(g0 + blockDim.x - 1, total - 1);
    int bmin = (int)(g0 / N);
    int bmax = (int)(g1 / N);

    if (threadIdx.x == 0) {
        inv4x4_f32(affine + bmin * 16, s_inv[0]);
        if (bmax != bmin) inv4x4_f32(affine + bmax * 16, s_inv[1]);
    }
    __syncthreads();

    if (gid >= total) return;
    int b = gid / N;
    int n = gid - b * N;

    // ---- affine transform ----
    const float* A = affine + b * 16;
    size_t vbase = ((size_t)b * N + n) * 3;
    float vx = verts[vbase + 0];
    float vy = verts[vbase + 1];
    float vz = verts[vbase + 2];

    float px = A[0] * vx + A[1] * vy + A[2]  * vz + A[3];
    float py = A[4] * vx + A[5] * vy + A[6]  * vz + A[7];
    float pz = A[8] * vx + A[9] * vy + A[10] * vz + A[11];

    const int HW  = H * W;
    const int DHW = D * HW;
    const ull* vol = g_vol + (size_t)b * (size_t)DHW;
    const float scale = 1.0f / (float)NUM_STEPS;
    const float dmax = (float)(D - 1), hmax = (float)(H - 1), wmax = (float)(W - 1);
    const ull MONE = pack2(-1.0f, -1.0f);

    float xd = px, xh = py, xw = pz;

    float cfd = 1e30f, cfh = 1e30f, cfw = 1e30f;
    int cell = -1;
    // rows: 0=d0h0, 1=d0h1, 2=d1h0, 3=d1h1
    ull c01e[4], c01d[4];     // ch0,1: even corner + (odd - even) diff, packed f32x2
    ull c2e0, c2d0, c2e1, c2d1;  // ch2: (row0,row1) and (row2,row3) packed

    #pragma unroll 1
    for (int s = 0; s < NUM_STEPS; s++) {
        float fd = xd - cfd;
        float fh = xh - cfh;
        float fw = xw - cfw;

        // in-cell iff all three fracs in [0,1): OR of bit patterns < bits(1.0f)
        unsigned ub = __float_as_uint(fd) | __float_as_uint(fh) | __float_as_uint(fw);
        if (ub >= 0x3F800000u) {
            float pdc = fminf(fmaxf(xd, 0.0f), dmax);
            float phc = fminf(fmaxf(xh, 0.0f), hmax);
            float pwc = fminf(fmaxf(xw, 0.0f), wmax);
            float fd0 = floorf(pdc), fh0 = floorf(phc), fw0 = floorf(pwc);
            int d0 = (int)fd0, h0 = (int)fh0, w0 = (int)fw0;
            fd = pdc - fd0; fh = phc - fh0; fw = pwc - fw0;
            cfd = fd0; cfh = fh0; cfw = fw0;

            int ncell = (d0 << 20) | (h0 << 10) | w0;
            if (ncell != cell) {
                cell = ncell;
                int d1 = min(d0 + 1, D - 1);
                int h1 = min(h0 + 1, H - 1);
                int w1 = min(w0 + 1, W - 1);
                int orow[4];
                orow[0] = d0 * HW + h0 * W;
                orow[1] = d0 * HW + h1 * W;
                orow[2] = d1 * HW + h0 * W;
                orow[3] = d1 * HW + h1 * W;
                float a2[4], b2[4];
                #pragma unroll
                for (int k = 0; k < 4; k++) {
                    ull va = __ldg(vol + orow[k] + w0);
                    ull vb = __ldg(vol + orow[k] + w1);
                    unsigned alo = (unsigned)va, ahi = (unsigned)(va >> 32);
                    unsigned blo = (unsigned)vb, bhi = (unsigned)(vb >> 32);
                    __half2 ha = *reinterpret_cast<__half2*>(&alo);
                    __half2 hb = *reinterpret_cast<__half2*>(&blo);
                    float2 fa = __half22float2(ha);
                    float2 fb = __half22float2(hb);
                    __half2 hza = *reinterpret_cast<__half2*>(&ahi);
                    __half2 hzb = *reinterpret_cast<__half2*>(&bhi);
                    a2[k] = __low2float(hza);
                    b2[k] = __low2float(hzb);
                    c01e[k] = pack2(fa.x, fa.y);
                    c01d[k] = pack2(fb.x - fa.x, fb.y - fa.y);
                }
                c2e0 = pack2(a2[0], a2[1]);
                c2d0 = pack2(b2[0] - a2[0], b2[1] - a2[1]);
                c2e1 = pack2(a2[2], a2[3]);
                c2d1 = pack2(b2[2] - a2[2], b2[3] - a2[3]);
            }
        }

        ull W2 = pack2(fw, fw);
        ull H2 = pack2(fh, fh);
        ull D2 = pack2(fd, fd);

        // ch0,1 : w-level via precomputed diffs, then diff-form h and d levels
        ull l0 = fma2(c01d[0], W2, c01e[0]);
        ull l1 = fma2(c01d[1], W2, c01e[1]);
        ull l2 = fma2(c01d[2], W2, c01e[2]);
        ull l3 = fma2(c01d[3], W2, c01e[3]);
        ull m0 = fma2(sub2(l1, l0, MONE), H2, l0);
        ull m1 = fma2(sub2(l3, l2, MONE), H2, l2);
        ull r01 = fma2(sub2(m1, m0, MONE), D2, m0);
        float s0, s1;
        unpack2(r01, s0, s1);

        // ch2 : packed w-level, scalar h/d levels
        ull qa = fma2(c2d0, W2, c2e0);   // (q_d0h0, q_d0h1)
        ull qb = fma2(c2d1, W2, c2e1);   // (q_d1h0, q_d1h1)
        float qa0, qa1, qb0, qb1;
        unpack2(qa, qa0, qa1);
        unpack2(qb, qb0, qb1);
        float q0 = fmaf(qa1 - qa0, fh, qa0);
        float q1 = fmaf(qb1 - qb0, fh, qb0);
        float s2 = fmaf(q1 - q0, fd, q0);

        xd = fmaf(s0, scale, xd);
        xh = fmaf(s1, scale, xh);
        xw = fmaf(s2, scale, xw);
    }

    // ---- outputs ----
    float fix = xd - px, fiy = xh - py, fiz = xw - pz;

    const float* Inv = s_inv[b - bmin];
    float ox = Inv[0] * xd + Inv[1] * xh + Inv[2]  * xw + Inv[3];
    float oy = Inv[4] * xd + Inv[5] * xh + Inv[6]  * xw + Inv[7];
    float oz = Inv[8] * xd + Inv[9] * xh + Inv[10] * xw + Inv[11];

    size_t pb = ((size_t)b * N + n) * 3;
    out[pb + 0] = ox;
    out[pb + 1] = oy;
    out[pb + 2] = oz;

    size_t fb = (size_t)B * N * 3 + ((size_t)b * 3) * (size_t)N + n;
    out[fb + 0 * (size_t)N] = fix;
    out[fb + 1 * (size_t)N] = fiy;
    out[fb + 2 * (size_t)N] = fiz;
}

// ---------------------------------------------------------------------------
// fallback: fp32 kernel (shapes that don't fit g_vol)
// ---------------------------------------------------------------------------
__global__ __launch_bounds__(128, 8)
void deform_plain_kernel(const float* __restrict__ verts,
                         const float* __restrict__ affine,
                         const float* __restrict__ flow,
                         float* __restrict__ out,
                         int B, int N, int D, int H, int W)
{
    __shared__ float s_inv[2][16];
    int gid = blockIdx.x * blockDim.x + threadIdx.x;
    long long total = (long long)B * N;
    long long g0 = (long long)blockIdx.x * blockDim.x;
    long long g1 = min(g0 + blockDim.x - 1, total - 1);
    int bmin = (int)(g0 / N);
    int bmax = (int)(g1 / N);
    if (threadIdx.x == 0) {
        inv4x4_f32(affine + bmin * 16, s_inv[0]);
        if (bmax != bmin) inv4x4_f32(affine + bmax * 16, s_inv[1]);
    }
    __syncthreads();
    if (gid >= total) return;
    int b = gid / N, n = gid - b * N;

    const float* A = affine + b * 16;
    size_t vbase = ((size_t)b * N + n) * 3;
    float vx = verts[vbase + 0], vy = verts[vbase + 1], vz = verts[vbase + 2];
    float px = A[0]*vx + A[1]*vy + A[2] *vz + A[3];
    float py = A[4]*vx + A[5]*vy + A[6] *vz + A[7];
    float pz = A[8]*vx + A[9]*vy + A[10]*vz + A[11];

    const int HW = H * W, DHW = D * HW;
    const float* base = flow + (size_t)b * 3 * (size_t)DHW;
    const float scale = 1.0f / (float)NUM_STEPS;
    const float dmax = (float)(D - 1), hmax = (float)(H - 1), wmax = (float)(W - 1);

    float xd = px, xh = py, xw = pz;
    float cfd = 1e30f, cfh = 1e30f, cfw = 1e30f;
    int cell = -1;
    float c0v[8], c1v[8], c2v[8];

    #pragma unroll 1
    for (int s = 0; s < NUM_STEPS; s++) {
        float fd = xd - cfd, fh = xh - cfh, fw = xw - cfw;
        unsigned ub = __float_as_uint(fd) | __float_as_uint(fh) | __float_as_uint(fw);
        if (ub >= 0x3F800000u) {
            float pdc = fminf(fmaxf(xd, 0.0f), dmax);
            float phc = fminf(fmaxf(xh, 0.0f), hmax);
            float pwc = fminf(fmaxf(xw, 0.0f), wmax);
            float fd0 = floorf(pdc), fh0 = floorf(phc), fw0 = floorf(pwc);
            int d0 = (int)fd0, h0 = (int)fh0, w0 = (int)fw0;
            fd = pdc - fd0; fh = phc - fh0; fw = pwc - fw0;
            cfd = fd0; cfh = fh0; cfw = fw0;
            int ncell = (d0 << 20) | (h0 << 10) | w0;
            if (ncell != cell) {
                cell = ncell;
                int d1 = min(d0 + 1, D - 1);
                int h1 = min(h0 + 1, H - 1);
                int w1 = min(w0 + 1, W - 1);
                int o[8];
                o[0] = d0*HW + h0*W + w0; o[1] = d0*HW + h0*W + w1;
                o[2] = d0*HW + h1*W + w0; o[3] = d0*HW + h1*W + w1;
                o[4] = d1*HW + h0*W + w0; o[5] = d1*HW + h0*W + w1;
                o[6] = d1*HW + h1*W + w0; o[7] = d1*HW + h1*W + w1;
                #pragma unroll
                for (int k = 0; k < 8; k++) {
                    c0v[k] = __ldg(base + o[k]);
                    c1v[k] = __ldg(base + DHW + o[k]);
                    c2v[k] = __ldg(base + 2*DHW + o[k]);
                }
            }
        }
        float omfw = 1.0f - fw, omfh = 1.0f - fh, omfd = 1.0f - fd;
        float smp[3];
        #pragma unroll
        for (int cc = 0; cc < 3; cc++) {
            const float* c = (cc == 0) ? c0v : (cc == 1) ? c1v : c2v;
            float a = c[0]*omfw + c[1]*fw;
            float bq = c[2]*omfw + c[3]*fw;
            float cq = c[4]*omfw + c[5]*fw;
            float dq = c[6]*omfw + c[7]*fw;
            float e = a*omfh + bq*fh;
            float f = cq*omfh + dq*fh;
            smp[cc] = e*omfd + f*fd;
        }
        xd = fmaf(smp[0], scale, xd);
        xh = fmaf(smp[1], scale, xh);
        xw = fmaf(smp[2], scale, xw);
    }

    float fix = xd - px, fiy = xh - py, fiz = xw - pz;
    const float* Inv = s_inv[b - bmin];
    float ox = Inv[0]*xd + Inv[1]*xh + Inv[2] *xw + Inv[3];
    float oy = Inv[4]*xd + Inv[5]*xh + Inv[6] *xw + Inv[7];
    float oz = Inv[8]*xd + Inv[9]*xh + Inv[10]*xw + Inv[11];
    size_t pb = ((size_t)b * N + n) * 3;
    out[pb + 0] = ox; out[pb + 1] = oy; out[pb + 2] = oz;
    size_t fb = (size_t)B * N * 3 + ((size_t)b * 3) * (size_t)N + n;
    out[fb + 0 * (size_t)N] = fix;
    out[fb + 1 * (size_t)N] = fiy;
    out[fb + 2 * (size_t)N] = fiz;
}

extern "C" void kernel_launch(void* const* d_in, const int* in_sizes, int n_in,
                              void* d_out, int out_size) {
    const float* verts  = (const float*)d_in[0];
    const float* affine = (const float*)d_in[1];
    const float* flow   = (const float*)d_in[2];
    float* out = (float*)d_out;

    int B = in_sizes[1] / 16;
    int N = in_sizes[0] / (3 * B);
    long long dhw = (long long)in_sizes[2] / (3LL * B);
    int D = (int)llrint(cbrt((double)dhw));
    int H = D, W = D;

    long long total = (long long)B * N;
    int threads = 128;
    int blocks = (int)((total + threads - 1) / threads);

    int DHW = D * H * W;
    if ((long long)B * DHW <= (long long)MAX_VOL && B <= 2 &&
        D <= 1023 && H <= 1023 && W <= 1023) {
        int quads = (DHW + 3) / 4;
        dim3 cgrid((quads + 255) / 256, B, 1);
        conv_kernel<<<cgrid, 256>>>(flow, DHW);
        deform_h4_kernel<<<blocks, threads>>>(verts, affine, out, B, N, D, H, W);
    } else {
        deform_plain_kernel<<<blocks, threads>>>(verts, affine, flow, out,
                                                 B, N, D, H, W);
    }
}

// round 15
// speedup vs baseline: 1.3175x; 1.1476x over previous
#include <cuda_runtime.h>
#include <math.h>

#define NUM_STEPS 30

typedef unsigned long long ull;

__device__ int g_ctr;

// ---------------------------------------------------------------------------
// packed f32x2 helpers (sm_103a)
// ---------------------------------------------------------------------------
__device__ __forceinline__ ull pack2(float lo, float hi) {
    ull r; asm("mov.b64 %0, {%1, %2};" : "=l"(r) : "f"(lo), "f"(hi)); return r;
}
__device__ __forceinline__ void unpack2(ull v, float& lo, float& hi) {
    asm("mov.b64 {%0, %1}, %2;" : "=f"(lo), "=f"(hi) : "l"(v));
}
__device__ __forceinline__ ull mul2(ull a, ull b) {
    ull r; asm("mul.rn.f32x2 %0, %1, %2;" : "=l"(r) : "l"(a), "l"(b)); return r;
}
__device__ __forceinline__ ull fma2(ull a, ull b, ull c) {
    ull r; asm("fma.rn.f32x2 %0, %1, %2, %3;" : "=l"(r) : "l"(a), "l"(b), "l"(c)); return r;
}
__device__ __forceinline__ ull lerp2(ull a, ull b, ull t, ull omt) {
    return fma2(b, t, mul2(a, omt));
}

// ---------------------------------------------------------------------------
// fp32 Gauss-Jordan 4x4 inverse (well-conditioned input)
// ---------------------------------------------------------------------------
__device__ void inv4x4_f32(const float* __restrict__ A, float* __restrict__ out) {
    float m[4][8];
    #pragma unroll
    for (int i = 0; i < 4; i++) {
        #pragma unroll
        for (int j = 0; j < 4; j++) m[i][j] = A[i * 4 + j];
        #pragma unroll
        for (int j = 0; j < 4; j++) m[i][4 + j] = (i == j) ? 1.0f : 0.0f;
    }
    #pragma unroll
    for (int col = 0; col < 4; col++) {
        int piv = col;
        float best = fabsf(m[col][col]);
        #pragma unroll
        for (int r = 0; r < 4; r++) {
            if (r > col) {
                float v = fabsf(m[r][col]);
                if (v > best) { best = v; piv = r; }
            }
        }
        if (piv != col) {
            #pragma unroll
            for (int j = 0; j < 8; j++) { float t = m[col][j]; m[col][j] = m[piv][j]; m[piv][j] = t; }
        }
        float inv = 1.0f / m[col][col];
        #pragma unroll
        for (int j = 0; j < 8; j++) m[col][j] *= inv;
        #pragma unroll
        for (int r = 0; r < 4; r++) {
            if (r != col) {
                float f = m[r][col];
                #pragma unroll
                for (int j = 0; j < 8; j++) m[r][j] = fmaf(-f, m[col][j], m[r][j]);
            }
        }
    }
    #pragma unroll
    for (int i = 0; i < 4; i++)
        #pragma unroll
        for (int j = 0; j < 4; j++)
            out[i * 4 + j] = m[i][4 + j];
}

// ---------------------------------------------------------------------------
// core per-point integration (r9 body, px recomputed at epilogue)
// ---------------------------------------------------------------------------
__device__ __forceinline__ void process_point(
    int gid, const float* __restrict__ verts, const float* __restrict__ affine,
    const float* __restrict__ flow, float* __restrict__ out,
    const float (*s_inv)[16], int B, int N, int D, int H, int W)
{
    int b = gid / N;
    int n = gid - b * N;

    const float* A = affine + b * 16;
    size_t vbase = ((size_t)b * N + n) * 3;
    float xd, xh, xw;
    {
        float vx = __ldg(verts + vbase + 0);
        float vy = __ldg(verts + vbase + 1);
        float vz = __ldg(verts + vbase + 2);
        xd = A[0] * vx + A[1] * vy + A[2]  * vz + A[3];
        xh = A[4] * vx + A[5] * vy + A[6]  * vz + A[7];
        xw = A[8] * vx + A[9] * vy + A[10] * vz + A[11];
    }

    const int HW  = H * W;
    const int DHW = D * HW;
    const float* base = flow + (size_t)b * 3 * (size_t)DHW;
    const float scale = 1.0f / (float)NUM_STEPS;
    const float dmax = (float)(D - 1), hmax = (float)(H - 1), wmax = (float)(W - 1);

    float cfd = 1e30f, cfh = 1e30f, cfw = 1e30f;
    int cell = -1;
    ull  c01[8];
    float c2[8];

    #pragma unroll 1
    for (int s = 0; s < NUM_STEPS; s++) {
        float fd = xd - cfd;
        float fh = xh - cfh;
        float fw = xw - cfw;

        float mn = fminf(fd, fminf(fh, fw));
        float mx = fmaxf(fd, fmaxf(fh, fw));
        if (!(mn >= 0.0f && mx < 1.0f)) {
            float pdc = fminf(fmaxf(xd, 0.0f), dmax);
            float phc = fminf(fmaxf(xh, 0.0f), hmax);
            float pwc = fminf(fmaxf(xw, 0.0f), wmax);
            float fd0 = floorf(pdc), fh0 = floorf(phc), fw0 = floorf(pwc);
            int d0 = (int)fd0, h0 = (int)fh0, w0 = (int)fw0;
            fd = pdc - fd0; fh = phc - fh0; fw = pwc - fw0;
            cfd = fd0; cfh = fh0; cfw = fw0;

            int ncell = (d0 << 20) | (h0 << 10) | w0;
            if (ncell != cell) {
                cell = ncell;
                int d1 = min(d0 + 1, D - 1);
                int h1 = min(h0 + 1, H - 1);
                int w1 = min(w0 + 1, W - 1);
                int rd0 = d0 * HW, rd1 = d1 * HW;
                int rh0 = h0 * W,  rh1 = h1 * W;
                int o[8];
                o[0] = rd0 + rh0 + w0; o[1] = rd0 + rh0 + w1;
                o[2] = rd0 + rh1 + w0; o[3] = rd0 + rh1 + w1;
                o[4] = rd1 + rh0 + w0; o[5] = rd1 + rh0 + w1;
                o[6] = rd1 + rh1 + w0; o[7] = rd1 + rh1 + w1;
                const float* p0 = base;
                const float* p1 = base + DHW;
                const float* p2 = base + 2 * DHW;
                #pragma unroll
                for (int k = 0; k < 8; k++) {
                    float a0 = __ldg(p0 + o[k]);
                    float a1 = __ldg(p1 + o[k]);
                    c2[k]  = __ldg(p2 + o[k]);
                    c01[k] = pack2(a0, a1);
                }
            }
        }

        float omfw = 1.0f - fw, omfh = 1.0f - fh, omfd = 1.0f - fd;
        ull W2  = pack2(fw, fw),   OW2 = pack2(omfw, omfw);
        ull H2  = pack2(fh, fh),   OH2 = pack2(omfh, omfh);
        ull D2  = pack2(fd, fd),   OD2 = pack2(omfd, omfd);

        ull l00 = lerp2(c01[0], c01[1], W2, OW2);
        ull l01 = lerp2(c01[2], c01[3], W2, OW2);
        ull l10 = lerp2(c01[4], c01[5], W2, OW2);
        ull l11 = lerp2(c01[6], c01[7], W2, OW2);
        ull m0  = lerp2(l00, l01, H2, OH2);
        ull m1  = lerp2(l10, l11, H2, OH2);
        ull r01 = lerp2(m0, m1, D2, OD2);
        float s0, s1;
        unpack2(r01, s0, s1);

        float q00 = c2[0] * omfw + c2[1] * fw;
        float q01 = c2[2] * omfw + c2[3] * fw;
        float q10 = c2[4] * omfw + c2[5] * fw;
        float q11 = c2[6] * omfw + c2[7] * fw;
        float q0  = q00 * omfh + q01 * fh;
        float q1  = q10 * omfh + q11 * fh;
        float s2  = q0 * omfd + q1 * fd;

        xd = fmaf(s0, scale, xd);
        xh = fmaf(s1, scale, xh);
        xw = fmaf(s2, scale, xw);
    }

    // ---- epilogue: recompute start position, then outputs ----
    float px, py, pz;
    {
        float vx = __ldg(verts + vbase + 0);
        float vy = __ldg(verts + vbase + 1);
        float vz = __ldg(verts + vbase + 2);
        px = A[0] * vx + A[1] * vy + A[2]  * vz + A[3];
        py = A[4] * vx + A[5] * vy + A[6]  * vz + A[7];
        pz = A[8] * vx + A[9] * vy + A[10] * vz + A[11];
    }
    float fix = xd - px, fiy = xh - py, fiz = xw - pz;

    const float* Inv = s_inv[b];
    float ox = Inv[0] * xd + Inv[1] * xh + Inv[2]  * xw + Inv[3];
    float oy = Inv[4] * xd + Inv[5] * xh + Inv[6]  * xw + Inv[7];
    float oz = Inv[8] * xd + Inv[9] * xh + Inv[10] * xw + Inv[11];

    size_t pb = ((size_t)b * N + n) * 3;
    out[pb + 0] = ox;
    out[pb + 1] = oy;
    out[pb + 2] = oz;

    size_t fb = (size_t)B * N * 3 + ((size_t)b * 3) * (size_t)N + n;
    out[fb + 0 * (size_t)N] = fix;
    out[fb + 1 * (size_t)N] = fiy;
    out[fb + 2 * (size_t)N] = fiz;
}

// ---------------------------------------------------------------------------
// persistent work-stealing kernel: one wave of CTAs, atomic point grabbing
// ---------------------------------------------------------------------------
__global__ __launch_bounds__(128, 8)
void deform_ws_kernel(const float* __restrict__ verts,
                      const float* __restrict__ affine,
                      const float* __restrict__ flow,
                      float* __restrict__ out,
                      int B, int N, int D, int H, int W, int total)
{
    __shared__ float s_inv[2][16];
    if (threadIdx.x < 2 && threadIdx.x < B)
        inv4x4_f32(affine + threadIdx.x * 16, s_inv[threadIdx.x]);
    __syncthreads();

    for (;;) {
        int i = atomicAdd(&g_ctr, 1);
        if (i >= total) return;
        process_point(i, verts, affine, flow, out, s_inv, B, N, D, H, W);
    }
}

// ---------------------------------------------------------------------------
// fallback: fixed-grid r9 kernel (B > 2)
// ---------------------------------------------------------------------------
__global__ __launch_bounds__(128, 8)
void deform_plain_kernel(const float* __restrict__ verts,
                         const float* __restrict__ affine,
                         const float* __restrict__ flow,
                         float* __restrict__ out,
                         int B, int N, int D, int H, int W)
{
    __shared__ float s_inv[2][16];
    int gid = blockIdx.x * blockDim.x + threadIdx.x;
    long long total = (long long)B * N;
    long long g0 = (long long)blockIdx.x * blockDim.x;
    long long g1 = min(g0 + blockDim.x - 1, total - 1);
    int bmin = (int)(g0 / N);
    int bmax = (int)(g1 / N);
    if (threadIdx.x == 0) {
        inv4x4_f32(affine + bmin * 16, s_inv[0]);
        if (bmax != bmin) inv4x4_f32(affine + bmax * 16, s_inv[1]);
    }
    __syncthreads();
    if (gid >= total) return;
    int b = gid / N;
    // remap so s_inv index works: s_inv[0]=bmin, s_inv[1]=bmax
    __shared__ float s_inv2[2][16];
    if (threadIdx.x == 0) {
        #pragma unroll
        for (int j = 0; j < 16; j++) { s_inv2[0][j] = s_inv[0][j]; s_inv2[1][j] = s_inv[1][j]; }
    }
    __syncthreads();
    // build a tiny local view indexed by b
    const float (*inv_view)[16] = (const float (*)[16])s_inv2;
    // process with adjusted indexing: process_point expects s_inv[b]
    // emulate by computing directly (b - bmin) selection:
    {
        // inline call with a shifted pointer trick: create local array of ptrs
        // simplest: copy the needed row into a per-thread view via index math
        int sel = b - bmin;   // 0 or 1
        // process_point indexes s_inv[b]; give it a pointer shifted so [b] == [sel]
        const float (*shifted)[16] = (const float (*)[16])(inv_view[sel] - (size_t)b * 16);
        process_point(gid, verts, affine, flow, out, shifted, B, N, D, H, W);
    }
}

extern "C" void kernel_launch(void* const* d_in, const int* in_sizes, int n_in,
                              void* d_out, int out_size) {
    const float* verts  = (const float*)d_in[0];
    const float* affine = (const float*)d_in[1];
    const float* flow   = (const float*)d_in[2];
    float* out = (float*)d_out;

    int B = in_sizes[1] / 16;
    int N = in_sizes[0] / (3 * B);
    long long dhw = (long long)in_sizes[2] / (3LL * B);
    int D = (int)llrint(cbrt((double)dhw));
    int H = D, W = D;

    long long total = (long long)B * N;
    if (total <= 0) return;

    if (B <= 2) {
        void* ctr_ptr = nullptr;
        cudaGetSymbolAddress(&ctr_ptr, g_ctr);
        cudaMemsetAsync(ctr_ptr, 0, sizeof(int));
        int blocks = 148 * 8;
        long long need = (total + 127) / 128;
        if (need < blocks) blocks = (int)need;
        deform_ws_kernel<<<blocks, 128>>>(verts, affine, flow, out,
                                          B, N, D, H, W, (int)total);
    } else {
        int threads = 128;
        int blocks = (int)((total + threads - 1) / threads);
        deform_plain_kernel<<<blocks, threads>>>(verts, affine, flow, out,
                                                 B, N, D, H, W);
    }
}